// round 16
// baseline (speedup 1.0000x reference)
#include <cuda_runtime.h>

#define BB 4096
#define TT 1024
#define NN 16
#define NPT 2   // packed pairs per lane: 4 lanes/row * 2 pairs * 2 = 16 filters
#define TQ (TT / 4)

// Quad-packed transposed currents: g_cur4[tq][b] = {cur[4tq..4tq+3]} for row b.
__device__ float4 g_cur4[(TQ + 4) * BB];

typedef unsigned long long u64;

__device__ __forceinline__ u64 pk2(float x, float y) {
    u64 r; asm("mov.b64 %0, {%1, %2};" : "=l"(r) : "f"(x), "f"(y)); return r;
}
__device__ __forceinline__ void upk2(u64 a, float& x, float& y) {
    asm("mov.b64 {%0, %1}, %2;" : "=f"(x), "=f"(y) : "l"(a));
}
__device__ __forceinline__ u64 fma2_(u64 a, u64 b, u64 c) {
    u64 d; asm("fma.rn.f32x2 %0, %1, %2, %3;" : "=l"(d) : "l"(a), "l"(b), "l"(c)); return d;
}
__device__ __forceinline__ u64 mul2_(u64 a, u64 b) {
    u64 d; asm("mul.rn.f32x2 %0, %1, %2;" : "=l"(d) : "l"(a), "l"(b)); return d;
}
__device__ __forceinline__ float tanh_a(float x) {
    float y; asm("tanh.approx.f32 %0, %1;" : "=f"(y) : "f"(x)); return y;
}

// ---------------------------------------------------------------------------
// Pass 1: transpose + quad-pack currents (B,T) -> g_cur4 (T/4, B) float4.
// ---------------------------------------------------------------------------
__global__ void transpose_kernel(const float* __restrict__ cur) {
    __shared__ float tile[32][33];
    const int tx = threadIdx.x, ty = threadIdx.y;
    const int t0 = blockIdx.x * 32, b0 = blockIdx.y * 32;
#pragma unroll
    for (int i = 0; i < 32; i += 8)
        tile[ty + i][tx] = cur[(size_t)(b0 + ty + i) * TT + (t0 + tx)];
    __syncthreads();
    float4 val;
    val.x = tile[tx][4 * ty + 0];
    val.y = tile[tx][4 * ty + 1];
    val.z = tile[tx][4 * ty + 2];
    val.w = tile[tx][4 * ty + 3];
    g_cur4[(size_t)((t0 >> 2) + ty) * BB + (b0 + tx)] = val;
}

// ---------------------------------------------------------------------------
// Pass 2: moment tower M1..M3 + CROSS-STEP-PIPELINED exchange.
//
//   M_k[t] = M_{k+1}[t-1] + cur_t*a_kc + th_{t-1}*b_kc   (k = 1,2,3)
//   M4[t-1] = sum_i d_i^4 V_i[t-1]   <- direct reduction, THE key change:
//
// The d^4 partial of v[t] is computed at the END of step t and its THREE
// INDEPENDENT bfly shuffles (masks 1,2,3) issue back-to-back (3 cyc, no
// mutual dependency -> no in-order issue bubble). Their results are summed
// a FULL STEP LATER (step t+1's M4), so the 26-cyc SHFL latency hides under
// step t+1's tanh stall. R9/R15 had two DEPENDENT shuffles: warp issue is
// in-order, so shfl#2 stalled the warp ~26 cyc EVERY step — the residual
// that survived every other ablation.
// ---------------------------------------------------------------------------
__global__ void __launch_bounds__(128, 1) gfr_kernel(
    const float* __restrict__ a, const float* __restrict__ b,
    const float* __restrict__ pc, const float* __restrict__ gb,
    const float* __restrict__ ds, const float* __restrict__ mc,
    const float* __restrict__ mfr, float* __restrict__ out)
{
    const int tid = threadIdx.x;
    const int sub = tid & 3;
    const int row = blockIdx.x * 32 + (tid >> 2);
    const int f0  = sub * 4;

    const float MFR = mfr[0];
    const float invmc = 1.f / mc[0];
    const float csN = invmc * (1.f / (float)NN);

    u64 av[NPT], bv[NPT], dv[NPT], d4v[NPT], v[NPT];
#pragma unroll
    for (int i = 0; i < NPT; i++) {
        const float dA = 1.f - ds[f0 + 2 * i], dB = 1.f - ds[f0 + 2 * i + 1];
        av[i]  = pk2(csN * a[f0 + 2 * i], csN * a[f0 + 2 * i + 1]);
        bv[i]  = pk2(csN * 1000.f * MFR * b[f0 + 2 * i],
                     csN * 1000.f * MFR * b[f0 + 2 * i + 1]);
        dv[i]  = pk2(dA, dB);
        d4v[i] = pk2(dA * dA * dA * dA, dB * dB * dB * dB);
        v[i] = 0ull;
    }
    float suma = 0.f, sumb = 0.f;
    float a1c = 0.f, b1c = 0.f, a2c = 0.f, b2c = 0.f, a3c = 0.f, b3c = 0.f;
#pragma unroll
    for (int n = 0; n < NN; n++) {
        const float dn = 1.f - ds[n];
        const float An = csN * a[n];
        const float Bn = csN * 1000.f * MFR * b[n];
        suma += a[n]; sumb += b[n];
        a1c += dn * An;           b1c += dn * Bn;
        a2c += dn * dn * An;      b2c += dn * dn * Bn;
        a3c += dn * dn * dn * An; b3c += dn * dn * dn * Bn;
    }
    const float ca = suma * csN;
    const float cb = 1000.f * MFR * sumb * csN;
    const float c0 = -gb[0] * invmc;
    const float q0 = pc[0] * pc[0], q1 = pc[1] * pc[1], q2 = pc[2] * pc[2],
                q3 = pc[3] * pc[3], q4 = pc[4] * pc[4];

    const float4* cp4 = g_cur4 + row;
    float* op = out + row + (size_t)sub * BB;
    float th = 0.f, M1 = 0.f, M2 = 0.f, M3 = 0.f;
    // pipelined exchange carries (v[-1] = 0 -> all zero)
    float Pp = 0.f, s1 = 0.f, s2 = 0.f, s3 = 0.f;

    float4 q0buf = __ldg(cp4);
    float4 q1buf = __ldg(cp4 + BB);

#define STEP(CUR, PRE, J)                                                   \
    {                                                                       \
        const float cur_ = (CUR);                                           \
        /* ---- th critical path ---- */                                    \
        const float m1p_ = M1 + (PRE);                                      \
        const float x_ = fmaf(th, cb, m1p_);                                \
        const float t1_ = fmaf(q1, x_, q0);                                 \
        const float t2_ = fmaf(q3, x_, q2);                                 \
        const float x2_ = x_ * x_;                                          \
        float p_ = fmaf(fmaf(q4, x2_, t2_), x2_, t1_);                      \
        p_ = fmaxf(p_, 0.f);                                                \
        const float thn_ = tanh_a(p_);                                      \
        /* ---- consume LAST step's shuffles: M4 = sum d^4 V[t-1] ---- */   \
        const float M4_ = (Pp + s1) + (s2 + s3);                            \
        /* ---- moment tower (OLD th) ---- */                               \
        const float M3n_ = fmaf(cur_, a3c, fmaf(th, b3c, M4_));             \
        const float M2n_ = fmaf(cur_, a2c, fmaf(th, b2c, M3));              \
        const float M1n_ = fmaf(cur_, a1c, fmaf(th, b1c, M2));              \
        /* ---- state update (OLD th) ---- */                               \
        const u64 cur2_ = pk2(cur_, cur_);                                  \
        const u64 th2_  = pk2(th, th);                                      \
        v[0] = fma2_(dv[0], v[0], fma2_(th2_, bv[0], mul2_(cur2_, av[0]))); \
        v[1] = fma2_(dv[1], v[1], fma2_(th2_, bv[1], mul2_(cur2_, av[1]))); \
        /* ---- new d^4 partial; 3 INDEPENDENT shuffles back-to-back ---- */\
        u64 s_ = fma2_(d4v[1], v[1], mul2_(d4v[0], v[0]));                  \
        float sx_, sy_; upk2(s_, sx_, sy_);                                 \
        const float Pn_ = sx_ + sy_;                                        \
        s1 = __shfl_xor_sync(0xFFFFFFFFu, Pn_, 1);                          \
        s2 = __shfl_xor_sync(0xFFFFFFFFu, Pn_, 2);                          \
        s3 = __shfl_xor_sync(0xFFFFFFFFu, Pn_, 3);                          \
        Pp = Pn_;                                                           \
        M1 = M1n_; M2 = M2n_; M3 = M3n_;                                    \
        if ((J) == sub) outv = thn_;                                        \
        th = thn_;                                                          \
    }

    for (int tq = 0; tq < TQ; tq += 2) {
        {
            float outv = 0.f;
            const float4 q = q0buf;
            q0buf = __ldg(cp4 + (size_t)(tq + 2) * BB);
            const float pr0 = fmaf(q.x, ca, c0), pr1 = fmaf(q.y, ca, c0);
            const float pr2 = fmaf(q.z, ca, c0), pr3 = fmaf(q.w, ca, c0);
            STEP(q.x, pr0, 0) STEP(q.y, pr1, 1) STEP(q.z, pr2, 2) STEP(q.w, pr3, 3)
            op[(size_t)tq * (4 * BB)] = MFR * outv;
        }
        {
            float outv = 0.f;
            const float4 q = q1buf;
            q1buf = __ldg(cp4 + (size_t)(tq + 3) * BB);
            const float pr0 = fmaf(q.x, ca, c0), pr1 = fmaf(q.y, ca, c0);
            const float pr2 = fmaf(q.z, ca, c0), pr3 = fmaf(q.w, ca, c0);
            STEP(q.x, pr0, 0) STEP(q.y, pr1, 1) STEP(q.z, pr2, 2) STEP(q.w, pr3, 3)
            op[(size_t)(tq + 1) * (4 * BB)] = MFR * outv;
        }
    }
#undef STEP
}

extern "C" void kernel_launch(void* const* d_in, const int* in_sizes, int n_in,
                              void* d_out, int out_size) {
    const float* currents = (const float*)d_in[0];
    const float* a   = (const float*)d_in[1];
    const float* b   = (const float*)d_in[2];
    const float* pc  = (const float*)d_in[3];
    const float* gb  = (const float*)d_in[4];
    const float* ds  = (const float*)d_in[5];
    const float* mc  = (const float*)d_in[6];
    const float* mfr = (const float*)d_in[7];
    float* out = (float*)d_out;

    dim3 tb(32, 8), tg(TT / 32, BB / 32);
    transpose_kernel<<<tg, tb>>>(currents);
    gfr_kernel<<<(4 * BB) / 128, 128>>>(a, b, pc, gb, ds, mc, mfr, out);
}